// round 17
// baseline (speedup 1.0000x reference)
#include <cuda_runtime.h>
#include <cstdint>

#define FEAT      256
#define PRE_CAP   16384
#define JT        16
#define JCH       (PRE_CAP / JT)
#define DEF_INSERT 999000
#define HB        2368                // hash blocks: 2 CTA waves
#define HT        (HB * 256)

typedef unsigned long long u64;

// ---------------- device scratch (no allocations allowed; zero-init) ----------------
__device__ u64      g_pre[PRE_CAP];        // ((0x7FFFFF - r) << 32) | index
__device__ int      g_npre;                // K1 atomic counter; reset by K3 (never read there)
__device__ int      g_npre2;               // snapshot written by K2, read by K3
__device__ int      g_rankp[PRE_CAP][JT];  // transposed: one 64B line per candidate

// ---------------- Threefry-2x32, 20 rounds, partitionable layout (JAX-exact) ----------------
__device__ __forceinline__ uint32_t rotl32(uint32_t x, int d) {
    return __funnelshift_l(x, x, d);
}

__device__ __forceinline__ uint32_t jax_bits32(uint32_t j) {
    const uint32_t k0 = 0u, k1 = 42u;
    const uint32_t ks2 = k0 ^ k1 ^ 0x1BD11BDAu;
    uint32_t x0 = 0u + k0, x1 = j + k1;
#define TF_R(r) { x0 += x1; x1 = rotl32(x1, (r)); x1 ^= x0; }
    TF_R(13) TF_R(15) TF_R(26) TF_R(6)   x0 += k1;  x1 += ks2 + 1u;
    TF_R(17) TF_R(29) TF_R(16) TF_R(24)  x0 += ks2; x1 += k0  + 2u;
    TF_R(13) TF_R(15) TF_R(26) TF_R(6)   x0 += k0;  x1 += k1  + 3u;
    TF_R(17) TF_R(29) TF_R(16) TF_R(24)  x0 += k1;  x1 += ks2 + 4u;
    TF_R(13) TF_R(15) TF_R(26) TF_R(6)   x0 += ks2; x1 += k0  + 5u;
#undef TF_R
    return x0 ^ x1;   // XOR-fold (jax_threefry_partitionable)
}

__device__ __forceinline__ int read_scalar(const int* p, int defv) {
    return p ? p[0] : defv;
}

__device__ __forceinline__ void warp_push(bool push, uint32_t bits, int j, int lane) {
    unsigned mask = __ballot_sync(0xFFFFFFFFu, push);
    if (mask) {
        int leader = __ffs(mask) - 1;
        int base = 0;
        if (lane == leader) base = atomicAdd(&g_npre, __popc(mask));
        base = __shfl_sync(0xFFFFFFFFu, base, leader);
        if (push) {
            int pos = base + __popc(mask & ((1u << lane) - 1u));
            if (pos < PRE_CAP) {
                uint32_t r = bits >> 9;   // 23-bit mantissa (rare path)
                g_pre[pos] = ((u64)(0x7FFFFFu - r) << 32) | (uint32_t)j;
            }
        }
    }
}

// ---------------- K1: hash all slots, <=2 per thread ----------------
__global__ void __launch_bounds__(256)
k_hash_push(const int* __restrict__ d_size, int max_size, int data_len, int nsamp) {
    int new_size = read_scalar(d_size, max_size) + data_len;
    if (new_size > max_size) new_size = max_size;
    if (new_size < 0) new_size = 0;

    // keep top ~1.125*nsamp expected survivors; compare raw bits (same set)
    uint32_t precut_bits = 0u;
    if (new_size > 0) {
        float keep_f = ((float)nsamp * 1.125f) * 8388608.0f / (float)new_size;
        u64 keep = (u64)keep_f;
        uint32_t precut = (keep >= 0x800000ull) ? 0u : (uint32_t)(0x800000ull - keep);
        precut_bits = precut << 9;
    }

    const int lane = threadIdx.x & 31;
    const int j0 = blockIdx.x * 256 + threadIdx.x;
    const int j1 = j0 + HT;

    uint32_t b0 = 0u, b1 = 0u;
    bool p0 = false, p1 = false;
    if (j0 < new_size) { b0 = jax_bits32((uint32_t)j0); p0 = (b0 >= precut_bits); }
    if (j1 < new_size) { b1 = jax_bits32((uint32_t)j1); p1 = (b1 >= precut_bits); }
    warp_push(p0, b0, j0, lane);
    warp_push(p1, b1, j1, lane);
}

// ---------------- K2: tiled exact rank (PDL: sync before consuming K1) ----------------
__global__ void k_rank() {
    cudaGridDependencySynchronize();   // wait for K1 completion (PDL overlap before this)

    int npre = g_npre;
    if (npre > PRE_CAP) npre = PRE_CAP;

    if (blockIdx.x == 0 && blockIdx.y == 0 && threadIdx.x == 0)
        g_npre2 = npre;   // snapshot for K3

    if ((int)(blockIdx.x * blockDim.x) >= npre) return;   // uniform per block

    __shared__ u64 sk[JCH];
    int chunk = (npre + JT - 1) / JT;
    int j0 = blockIdx.y * chunk;
    int j1 = j0 + chunk; if (j1 > npre) j1 = npre;
    if (j0 >= npre) return;   // empty tile: entry stays stale-correct across replays
    for (int j = j0 + threadIdx.x; j < j1; j += blockDim.x)
        sk[j - j0] = g_pre[j];
    __syncthreads();

    int t = blockIdx.x * blockDim.x + threadIdx.x;
    u64 mykey = (t < npre) ? g_pre[t] : ~0ull;
    int len = j1 - j0;
    int cnt = 0, j = 0;
    for (; j + 4 <= len; j += 4) {
        cnt += (sk[j]     < mykey);
        cnt += (sk[j + 1] < mykey);
        cnt += (sk[j + 2] < mykey);
        cnt += (sk[j + 3] < mykey);
    }
    for (; j < len; ++j) cnt += (sk[j] < mykey);
    if (t < npre) g_rankp[t][blockIdx.y] = cnt;   // one 64B line per candidate
}

// ---------------- K3: fused finalize + gather (PDL: sync before consuming K2) ----------------
__global__ void __launch_bounds__(256)
k_rank_gather(const float* __restrict__ buf, const float* __restrict__ tr,
              const int* __restrict__ d_ins, float* __restrict__ out,
              int max_size, int data_len, int nsamp) {
    cudaGridDependencySynchronize();   // wait for K2 completion

    // reset K1's counter for the next run/replay; no thread here reads g_npre
    if (blockIdx.x == 0 && threadIdx.x == 0) g_npre = 0;

    int npre = g_npre2;
    if (npre > PRE_CAP) npre = PRE_CAP;

    const int lane   = threadIdx.x & 31;
    const int warp   = (blockIdx.x * blockDim.x + threadIdx.x) >> 5;
    const int nwarps = (gridDim.x * blockDim.x) >> 5;
    const long p_ins = (long)(read_scalar(d_ins, DEF_INSERT) % max_size);

    for (int t = warp; t < npre; t += nwarps) {
        // both loads issued before the reduction (independent)
        int part = (lane < JT) ? g_rankp[t][lane] : 0;
        u64 key  = g_pre[t];
        int rank = __reduce_add_sync(0xFFFFFFFFu, part);
        if (rank >= nsamp) continue;

        uint32_t idx = (uint32_t)key;
        long off = (long)idx - p_ins;
        if (off < 0) off += max_size;
        const float4* src = (off < (long)data_len)
            ? (const float4*)(tr + (size_t)off * FEAT)
            : (const float4*)(buf + (size_t)idx * FEAT);
        float4* dst = (float4*)(out + (size_t)rank * FEAT);

        float4 v0 = src[lane];
        float4 v1 = src[lane + 32];
        dst[lane]      = v0;
        dst[lane + 32] = v1;
    }
}

// ---------------- launcher (PDL-chained) ----------------
extern "C" void kernel_launch(void* const* d_in, const int* in_sizes, int n_in,
                              void* d_out, int out_size) {
    // Classify inputs by element count (robust to ordering):
    int i_buf = -1, i_tr = -1;
    int sc[3] = { -1, -1, -1 };
    int nsc = 0;
    for (int i = 0; i < n_in; ++i) {
        if (in_sizes[i] > 100000000)      i_buf = i;
        else if (in_sizes[i] > 1000000)   i_tr  = i;
        else if (in_sizes[i] >= 1 && in_sizes[i] <= 4 && nsc < 3) sc[nsc++] = i;
    }
    if (i_buf < 0) i_buf = 0;
    if (i_tr  < 0) i_tr  = 1;

    const float* buf   = (const float*)d_in[i_buf];
    const float* tr    = (const float*)d_in[i_tr];
    const int*   d_ins = (sc[0] >= 0) ? (const int*)d_in[sc[0]] : nullptr;
    const int*   d_sz  = (sc[1] >= 0) ? (const int*)d_in[sc[1]] : nullptr;

    int max_size = in_sizes[i_buf] / FEAT;   // 1,000,000
    int data_len = in_sizes[i_tr]  / FEAT;   // 16,384
    int nsamp    = out_size        / FEAT;   // 4,096

    // K1: normal launch
    k_hash_push<<<HB, 256>>>(d_sz, max_size, data_len, nsamp);

    // PDL attribute: allow overlap with predecessor; in-kernel grid sync enforces data dep
    cudaLaunchAttribute pdl[1];
    pdl[0].id = cudaLaunchAttributeProgrammaticStreamSerialization;
    pdl[0].val.programmaticStreamSerializationAllowed = 1;

    {   // K2
        cudaLaunchConfig_t cfg = {};
        cfg.gridDim  = dim3(PRE_CAP / 256, JT);   // (64, 16)
        cfg.blockDim = dim3(256, 1, 1);
        cfg.attrs = pdl;
        cfg.numAttrs = 1;
        cudaLaunchKernelEx(&cfg, k_rank);
    }
    {   // K3
        cudaLaunchConfig_t cfg = {};
        cfg.gridDim  = dim3(768, 1, 1);           // 6144 warps
        cfg.blockDim = dim3(256, 1, 1);
        cfg.attrs = pdl;
        cfg.numAttrs = 1;
        cudaLaunchKernelEx(&cfg, k_rank_gather,
                           buf, tr, d_ins, (float*)d_out,
                           max_size, data_len, nsamp);
    }
}